// round 12
// baseline (speedup 1.0000x reference)
#include <cuda_runtime.h>
#include <cuda_fp16.h>
#include <cstdint>
#include <math.h>

#define DI __device__ __forceinline__

// ---------------- problem sizes ----------------
constexpr int BB   = 4;
constexpr int LL   = 8192;
constexpr int DD   = 1024;
constexpr int MTOT = BB * LL;     // 32768
constexpr int KTOT = 1024;

// GEMM tiling: 128x128 CTA tile, 8 warps (4Mx2N), 32x64 warp tiles, BK=64, 2 CTAs/SM
constexpr int BM = 128, BN = 128, BK = 64;
constexpr int NKC = KTOT / BK;            // 16
constexpr int KP  = 72;                   // smem pitch in halfs (144B rows, conflict-free)
constexpr int ASTAGE = BM * KP;           // 9216 halfs
constexpr int BSTAGE = BN * KP;           // 9216 halfs
constexpr int STAGE_H = ASTAGE + BSTAGE;  // 18432 halfs = 36864 B
constexpr int STAGES = 3;
constexpr int SMEM_BYTES = STAGES * STAGE_H * 2;   // 110592 B -> 2 CTAs/SM
constexpr int EXPITCH = 68;               // epilogue exchange pitch (floats)

// scan chunking
constexpr int NC = 128;
constexpr int CL = LL / NC;               // 64
constexpr int NCHAIN = BB * DD;           // 4096

// ---------------- device scratch ----------------
__device__ __half g_xh[(size_t)MTOT * KTOT];    // fp16 x
__device__ __half g_wh[(size_t)4 * DD * KTOT];  // fp16 weights, [gate][n][k]; gate order f,i,ig,og
__device__ __half g_f [(size_t)MTOT * DD];      // sigmoid forget gate (fp16)
__device__ __half g_I [(size_t)MTOT * DD];      // tanh(zi)*sig(zig) fused input (fp16)
__device__ __half g_og[(size_t)MTOT * DD];      // sigmoid output gate (fp16)
__device__ float g_cA[NC * NCHAIN];
__device__ float g_cB[NC * NCHAIN];
__device__ float g_cr[NC * NCHAIN];

// ---------------- helpers ----------------
DI uint32_t smem_u32(const void* p) {
    uint32_t a;
    asm("{ .reg .u64 t; cvta.to.shared.u64 t, %1; cvt.u32.u64 %0, t; }" : "=r"(a) : "l"(p));
    return a;
}
DI void cp16(uint32_t dst, const void* src) {
    asm volatile("cp.async.cg.shared.global [%0], [%1], 16;" :: "r"(dst), "l"(src));
}
DI void cp_commit() { asm volatile("cp.async.commit_group;" ::: "memory"); }
template <int N> DI void cp_wait() {
    asm volatile("cp.async.wait_group %0;" :: "n"(N) : "memory");
}
DI void ldsm4(uint32_t& r0, uint32_t& r1, uint32_t& r2, uint32_t& r3, uint32_t addr) {
    asm volatile("ldmatrix.sync.aligned.m8n8.x4.shared.b16 {%0,%1,%2,%3}, [%4];"
                 : "=r"(r0), "=r"(r1), "=r"(r2), "=r"(r3) : "r"(addr));
}
DI void mma_f16(float& c0, float& c1, float& c2, float& c3,
                uint32_t a0, uint32_t a1, uint32_t a2, uint32_t a3,
                uint32_t b0, uint32_t b1) {
    asm volatile(
        "mma.sync.aligned.m16n8k16.row.col.f32.f16.f16.f32 "
        "{%0,%1,%2,%3}, {%4,%5,%6,%7}, {%8,%9}, {%0,%1,%2,%3};"
        : "+f"(c0), "+f"(c1), "+f"(c2), "+f"(c3)
        : "r"(a0), "r"(a1), "r"(a2), "r"(a3), "r"(b0), "r"(b1));
}
DI float sigf(float z) { return 1.0f / (1.0f + __expf(-z)); }
DI float tanhfast(float z) { return 1.0f - 2.0f / (1.0f + __expf(2.0f * z)); }

// ---------------- prep: fp32 -> fp16 ----------------
__global__ void prep_x_kernel(const float* __restrict__ x) {
    size_t i = (size_t)blockIdx.x * blockDim.x + threadIdx.x;
    float4 v0 = reinterpret_cast<const float4*>(x)[2 * i];
    float4 v1 = reinterpret_cast<const float4*>(x)[2 * i + 1];
    __half2 h[4];
    h[0] = __floats2half2_rn(v0.x, v0.y);
    h[1] = __floats2half2_rn(v0.z, v0.w);
    h[2] = __floats2half2_rn(v1.x, v1.y);
    h[3] = __floats2half2_rn(v1.z, v1.w);
    reinterpret_cast<uint4*>(g_xh)[i] = *reinterpret_cast<uint4*>(h);
}

__global__ void prep_w_kernel(const float* __restrict__ Wf, const float* __restrict__ Wi,
                              const float* __restrict__ Wig, const float* __restrict__ Wog) {
    __shared__ float t[32][33];
    int g = blockIdx.z;
    const float* W = (g == 0) ? Wf : (g == 1) ? Wi : (g == 2) ? Wig : Wog;
    int n0 = blockIdx.x * 32, k0 = blockIdx.y * 32;
    int tx = threadIdx.x, ty = threadIdx.y;
    t[ty][tx] = W[(size_t)(k0 + ty) * 1024 + n0 + tx];
    __syncthreads();
    g_wh[(size_t)(g * 1024 + n0 + ty) * 1024 + (k0 + tx)] = __float2half_rn(t[tx][ty]);
}

// ---------------- fp16 GEMM with fused i*ig epilogue ----------------
// nTile mapping: 0..7 -> forget gate (128 cols each)
//                8..23 -> pair tiles: cols 0..63 = W_i[:,c0..c0+64), cols 64..127 = W_ig same cols
//                24..31 -> output gate
__global__ void __launch_bounds__(256, 2)
gemm_kernel(const float* __restrict__ bf, const float* __restrict__ bi,
            const float* __restrict__ big, const float* __restrict__ bog) {
    extern __shared__ __half sm[];
    const uint32_t sb = smem_u32(sm);

    const int tid  = threadIdx.x;
    const int wid  = tid >> 5, lane = tid & 31;
    const int lane4 = lane & 3, laneg = lane >> 2;
    const int warpM = wid & 3;          // 4 warps along M (32 rows each)
    const int warpN = wid >> 2;         // 2 warps along N (64 cols each)
    const int nTile = blockIdx.x;       // 0..31
    const int mTile = blockIdx.y;       // 0..255

    const bool isPair = (nTile >= 8) && (nTile < 24);
    const __half* B0;
    const __half* B1;
    int c0 = 0;      // pair col base
    int nbase = 0;   // f/og col base
    if (nTile < 8) {
        nbase = nTile * 128;
        B0 = g_wh + (size_t)nbase * KTOT;
        B1 = B0 + (size_t)64 * KTOT;
    } else if (isPair) {
        c0 = (nTile - 8) * 64;
        B0 = g_wh + (size_t)(1024 + c0) * KTOT;   // W_i rows
        B1 = g_wh + (size_t)(2048 + c0) * KTOT;   // W_ig rows
    } else {
        nbase = (nTile - 24) * 128;
        B0 = g_wh + (size_t)(3 * 1024 + nbase) * KTOT;
        B1 = B0 + (size_t)64 * KTOT;
    }

    const __half* Abase = g_xh + (size_t)mTile * BM * KTOT;

    auto load_chunk = [&](int kc, int s) {
        const uint32_t sA = sb + s * (STAGE_H * 2);
        const uint32_t sB = sA + ASTAGE * 2;
        const __half* gA = Abase + kc * BK;
        #pragma unroll
        for (int i = 0; i < 4; i++) {                 // A: 1024 x 16B chunks
            int c = tid + i * 256;
            int row = c >> 3, seg = (c & 7) * 8;
            cp16(sA + (row * KP + seg) * 2, gA + (size_t)row * KTOT + seg);
        }
        #pragma unroll
        for (int i = 0; i < 4; i++) {                 // B: 1024 x 16B chunks
            int c = tid + i * 256;
            int row = c >> 3, seg = (c & 7) * 8;
            const __half* src = (row < 64) ? (B0 + (size_t)row * KTOT)
                                           : (B1 + (size_t)(row - 64) * KTOT);
            cp16(sB + (row * KP + seg) * 2, src + kc * BK + seg);
        }
        cp_commit();
    };

    float acc[2][8][4];
    #pragma unroll
    for (int mf = 0; mf < 2; mf++)
        #pragma unroll
        for (int nf = 0; nf < 8; nf++)
            #pragma unroll
            for (int j = 0; j < 4; j++) acc[mf][nf][j] = 0.0f;

    uint32_t aOff[2], bOff[4];
    #pragma unroll
    for (int mf = 0; mf < 2; mf++)
        aOff[mf] = (uint32_t)(((warpM * 32 + mf * 16 + (lane & 15)) * KP + (lane >> 4) * 8) * 2);
    #pragma unroll
    for (int p = 0; p < 4; p++)
        bOff[p] = (uint32_t)(((warpN * 64 + p * 16 + (lane & 7) + (lane >> 4) * 8) * KP
                              + ((lane >> 3) & 1) * 8) * 2) + ASTAGE * 2;

    load_chunk(0, 0);
    load_chunk(1, 1);

    for (int kc = 0; kc < NKC; kc++) {
        const int s = kc % STAGES;
        if (kc + 1 < NKC) cp_wait<1>(); else cp_wait<0>();
        __syncthreads();
        if (kc + 2 < NKC) load_chunk(kc + 2, (kc + 2) % STAGES);

        const uint32_t st = sb + s * (STAGE_H * 2);
        #pragma unroll
        for (int kf = 0; kf < 4; kf++) {
            const uint32_t kb = kf * 32;
            uint32_t a[2][4];
            #pragma unroll
            for (int mf = 0; mf < 2; mf++)
                ldsm4(a[mf][0], a[mf][1], a[mf][2], a[mf][3], st + aOff[mf] + kb);
            uint32_t b[8][2];
            #pragma unroll
            for (int p = 0; p < 4; p++)
                ldsm4(b[2 * p][0], b[2 * p][1], b[2 * p + 1][0], b[2 * p + 1][1],
                      st + bOff[p] + kb);
            #pragma unroll
            for (int mf = 0; mf < 2; mf++)
                #pragma unroll
                for (int nf = 0; nf < 8; nf++)
                    mma_f16(acc[mf][nf][0], acc[mf][nf][1], acc[mf][nf][2], acc[mf][nf][3],
                            a[mf][0], a[mf][1], a[mf][2], a[mf][3],
                            b[nf][0], b[nf][1]);
        }
    }

    if (isPair) {
        // -------- fused i*ig epilogue --------
        float* ex = reinterpret_cast<float*>(sm);   // 128 x 64 exchange (pitch EXPITCH)
        __syncthreads();                             // stage smem now dead
        if (warpN == 1) {
            // store biased z_ig into exchange buffer
            #pragma unroll
            for (int nf = 0; nf < 8; nf++) {
                const int col = nf * 8 + 2 * lane4;
                const float bz0 = big[c0 + col], bz1 = big[c0 + col + 1];
                #pragma unroll
                for (int mf = 0; mf < 2; mf++) {
                    const int rl = warpM * 32 + mf * 16 + laneg;
                    ex[rl * EXPITCH + col]           = acc[mf][nf][0] + bz0;
                    ex[rl * EXPITCH + col + 1]       = acc[mf][nf][1] + bz1;
                    ex[(rl + 8) * EXPITCH + col]     = acc[mf][nf][2] + bz0;
                    ex[(rl + 8) * EXPITCH + col + 1] = acc[mf][nf][3] + bz1;
                }
            }
        }
        __syncthreads();
        if (warpN == 0) {
            #pragma unroll
            for (int nf = 0; nf < 8; nf++) {
                const int col = nf * 8 + 2 * lane4;
                const float bz0 = bi[c0 + col], bz1 = bi[c0 + col + 1];
                #pragma unroll
                for (int mf = 0; mf < 2; mf++) {
                    const int rl = warpM * 32 + mf * 16 + laneg;
                    const int r0 = mTile * BM + rl;
                    float i0 = tanhfast(acc[mf][nf][0] + bz0) * sigf(ex[rl * EXPITCH + col]);
                    float i1 = tanhfast(acc[mf][nf][1] + bz1) * sigf(ex[rl * EXPITCH + col + 1]);
                    float i2 = tanhfast(acc[mf][nf][2] + bz0) * sigf(ex[(rl + 8) * EXPITCH + col]);
                    float i3 = tanhfast(acc[mf][nf][3] + bz1) * sigf(ex[(rl + 8) * EXPITCH + col + 1]);
                    *reinterpret_cast<__half2*>(g_I + (size_t)r0 * DD + c0 + col) =
                        __floats2half2_rn(i0, i1);
                    *reinterpret_cast<__half2*>(g_I + (size_t)(r0 + 8) * DD + c0 + col) =
                        __floats2half2_rn(i2, i3);
                }
            }
        }
    } else {
        // -------- plain sigmoid epilogue (f / og) --------
        const float* bias = (nTile < 8) ? bf : bog;
        __half* oA = (nTile < 8) ? g_f : g_og;
        #pragma unroll
        for (int nf = 0; nf < 8; nf++) {
            const int d = nbase + warpN * 64 + nf * 8 + 2 * lane4;
            const float bz0 = bias[d], bz1 = bias[d + 1];
            #pragma unroll
            for (int mf = 0; mf < 2; mf++) {
                const int r0 = mTile * BM + warpM * 32 + mf * 16 + laneg;
                float o0 = sigf(acc[mf][nf][0] + bz0);
                float o1 = sigf(acc[mf][nf][1] + bz1);
                float o2 = sigf(acc[mf][nf][2] + bz0);
                float o3 = sigf(acc[mf][nf][3] + bz1);
                *reinterpret_cast<__half2*>(oA + (size_t)r0 * DD + d) = __floats2half2_rn(o0, o1);
                *reinterpret_cast<__half2*>(oA + (size_t)(r0 + 8) * DD + d) = __floats2half2_rn(o2, o3);
            }
        }
    }
}

// ---------------- scan kernels (2 chains per thread via half2) ----------------
__global__ void scan_pass1() {
    int p = blockIdx.x * 256 + threadIdx.x;         // 0..511 half2 lane
    int c = blockIdx.y, b = blockIdx.z;
    size_t base = ((size_t)(b * LL + c * CL)) * (DD / 2) + p;
    const __half2* F2p = reinterpret_cast<const __half2*>(g_f);
    const __half2* I2p = reinterpret_cast<const __half2*>(g_I);
    float2 a = make_float2(1.0f, 1.0f);
    float2 s = make_float2(0.0f, 0.0f);
    for (int t = 0; t < CL; t++) {
        size_t idx = base + (size_t)t * (DD / 2);
        float2 F = __half22float2(F2p[idx]);
        float2 I = __half22float2(I2p[idx]);
        s.x = fmaf(F.x, s.x, I.x);
        s.y = fmaf(F.y, s.y, I.y);
        a.x *= F.x; a.y *= F.y;
    }
    int chain = b * DD + 2 * p;
    g_cA[c * NCHAIN + chain]     = a.x;
    g_cA[c * NCHAIN + chain + 1] = a.y;
    g_cB[c * NCHAIN + chain]     = s.x;
    g_cB[c * NCHAIN + chain + 1] = s.y;
}

__global__ void scan_pass2(const float* __restrict__ lh) {
    int chain = blockIdx.x * 256 + threadIdx.x;     // 0..4095
    float carry = lh[chain & (DD - 1)];
    for (int c = 0; c < NC; c++) {
        g_cr[c * NCHAIN + chain] = carry;
        carry = fmaf(g_cA[c * NCHAIN + chain], carry, g_cB[c * NCHAIN + chain]);
    }
}

__global__ void scan_pass3(float* __restrict__ y) {
    int p = blockIdx.x * 256 + threadIdx.x;         // 0..511 half2 lane
    int c = blockIdx.y, b = blockIdx.z;
    int chain = b * DD + 2 * p;
    float2 h;
    h.x = g_cr[c * NCHAIN + chain];
    h.y = g_cr[c * NCHAIN + chain + 1];
    size_t base = ((size_t)(b * LL + c * CL)) * (DD / 2) + p;
    const __half2* F2p  = reinterpret_cast<const __half2*>(g_f);
    const __half2* I2p  = reinterpret_cast<const __half2*>(g_I);
    const __half2* Og2p = reinterpret_cast<const __half2*>(g_og);
    for (int t = 0; t < CL; t++) {
        size_t idx = base + (size_t)t * (DD / 2);
        float2 F = __half22float2(F2p[idx]);
        float2 I = __half22float2(I2p[idx]);
        float2 Og = __half22float2(Og2p[idx]);
        h.x = fmaf(F.x, h.x, I.x);
        h.y = fmaf(F.y, h.y, I.y);
        float2 o;
        o.x = tanhfast(h.x) * Og.x;
        o.y = tanhfast(h.y) * Og.y;
        reinterpret_cast<float2*>(y)[idx] = o;
    }
}

// ---------------- launch ----------------
extern "C" void kernel_launch(void* const* d_in, const int* in_sizes, int n_in,
                              void* d_out, int out_size) {
    const float* x   = (const float*)d_in[0];
    const float* Wf  = (const float*)d_in[1];
    const float* bf  = (const float*)d_in[2];
    const float* Wi  = (const float*)d_in[3];
    const float* bi  = (const float*)d_in[4];
    const float* Wig = (const float*)d_in[5];
    const float* big = (const float*)d_in[6];
    const float* Wog = (const float*)d_in[7];
    const float* bog = (const float*)d_in[8];
    const float* lh  = (const float*)d_in[9];
    float* y = (float*)d_out;

    cudaFuncSetAttribute(gemm_kernel, cudaFuncAttributeMaxDynamicSharedMemorySize, SMEM_BYTES);

    prep_x_kernel<<<16384, 256>>>(x);
    prep_w_kernel<<<dim3(32, 32, 4), dim3(32, 32)>>>(Wf, Wi, Wig, Wog);
    gemm_kernel<<<dim3(32, 256), 256, SMEM_BYTES>>>(bf, bi, big, bog);
    scan_pass1<<<dim3(2, NC, 4), 256>>>();
    scan_pass2<<<16, 256>>>(lh);
    scan_pass3<<<dim3(2, NC, 4), 256>>>(y);
}

// round 15
// speedup vs baseline: 1.0493x; 1.0493x over previous
#include <cuda_runtime.h>
#include <cuda_fp16.h>
#include <cstdint>
#include <math.h>

#define DI __device__ __forceinline__

// ---------------- problem sizes ----------------
constexpr int BB   = 4;
constexpr int LL   = 8192;
constexpr int DD   = 1024;
constexpr int MTOT = BB * LL;     // 32768
constexpr int KTOT = 1024;

// GEMM tiling: 128x128 CTA tile, 8 warps (4Mx2N), 32x64 warp tiles, BK=64, 2 CTAs/SM
constexpr int BM = 128, BN = 128, BK = 64;
constexpr int NKC = KTOT / BK;            // 16
constexpr int KP  = 72;                   // smem pitch in halfs (144B rows, conflict-free)
constexpr int ASTAGE = BM * KP;           // 9216 halfs
constexpr int BSTAGE = BN * KP;           // 9216 halfs
constexpr int STAGE_H = ASTAGE + BSTAGE;  // 18432 halfs = 36864 B
constexpr int STAGES = 3;
constexpr int SMEM_BYTES = STAGES * STAGE_H * 2;   // 110592 B -> 2 CTAs/SM

// scan chunking
constexpr int NC = 128;
constexpr int CL = LL / NC;               // 64
constexpr int NCHAIN = BB * DD;           // 4096

// ---------------- device scratch ----------------
// g_wh row layout: [0,1024)      = W_f columns (n-major)
//                  [1024,3072)   = interleaved pair: row 1024+2c = W_i col c,
//                                                    row 1024+2c+1 = W_ig col c
//                  [3072,4096)   = W_og columns
__device__ __half g_xh[(size_t)MTOT * KTOT];    // fp16 x
__device__ __half g_wh[(size_t)4 * DD * KTOT];  // fp16 weights [n][k]
__device__ __half g_f [(size_t)MTOT * DD];      // sigmoid forget gate (fp16)
__device__ __half g_I [(size_t)MTOT * DD];      // tanh(zi)*sig(zig) fused input (fp16)
__device__ __half g_og[(size_t)MTOT * DD];      // sigmoid output gate (fp16)
__device__ float g_cA[NC * NCHAIN];
__device__ float g_cB[NC * NCHAIN];
__device__ float g_cr[NC * NCHAIN];

// ---------------- helpers ----------------
DI uint32_t smem_u32(const void* p) {
    uint32_t a;
    asm("{ .reg .u64 t; cvta.to.shared.u64 t, %1; cvt.u32.u64 %0, t; }" : "=r"(a) : "l"(p));
    return a;
}
DI void cp16(uint32_t dst, const void* src) {
    asm volatile("cp.async.cg.shared.global [%0], [%1], 16;" :: "r"(dst), "l"(src));
}
DI void cp_commit() { asm volatile("cp.async.commit_group;" ::: "memory"); }
template <int N> DI void cp_wait() {
    asm volatile("cp.async.wait_group %0;" :: "n"(N) : "memory");
}
DI void ldsm4(uint32_t& r0, uint32_t& r1, uint32_t& r2, uint32_t& r3, uint32_t addr) {
    asm volatile("ldmatrix.sync.aligned.m8n8.x4.shared.b16 {%0,%1,%2,%3}, [%4];"
                 : "=r"(r0), "=r"(r1), "=r"(r2), "=r"(r3) : "r"(addr));
}
DI void mma_f16(float& c0, float& c1, float& c2, float& c3,
                uint32_t a0, uint32_t a1, uint32_t a2, uint32_t a3,
                uint32_t b0, uint32_t b1) {
    asm volatile(
        "mma.sync.aligned.m16n8k16.row.col.f32.f16.f16.f32 "
        "{%0,%1,%2,%3}, {%4,%5,%6,%7}, {%8,%9}, {%0,%1,%2,%3};"
        : "+f"(c0), "+f"(c1), "+f"(c2), "+f"(c3)
        : "r"(a0), "r"(a1), "r"(a2), "r"(a3), "r"(b0), "r"(b1));
}
DI float sigf(float z) { return 1.0f / (1.0f + __expf(-z)); }
DI float tanhfast(float z) { return 1.0f - 2.0f / (1.0f + __expf(2.0f * z)); }

// ---------------- prep: fp32 -> fp16 ----------------
__global__ void prep_x_kernel(const float* __restrict__ x) {
    size_t i = (size_t)blockIdx.x * blockDim.x + threadIdx.x;
    float4 v0 = reinterpret_cast<const float4*>(x)[2 * i];
    float4 v1 = reinterpret_cast<const float4*>(x)[2 * i + 1];
    __half2 h[4];
    h[0] = __floats2half2_rn(v0.x, v0.y);
    h[1] = __floats2half2_rn(v0.z, v0.w);
    h[2] = __floats2half2_rn(v1.x, v1.y);
    h[3] = __floats2half2_rn(v1.z, v1.w);
    reinterpret_cast<uint4*>(g_xh)[i] = *reinterpret_cast<uint4*>(h);
}

__global__ void prep_w_kernel(const float* __restrict__ Wf, const float* __restrict__ Wi,
                              const float* __restrict__ Wig, const float* __restrict__ Wog) {
    __shared__ float t[32][33];
    int g = blockIdx.z;
    const float* W = (g == 0) ? Wf : (g == 1) ? Wi : (g == 2) ? Wig : Wog;
    int n0 = blockIdx.x * 32, k0 = blockIdx.y * 32;
    int tx = threadIdx.x, ty = threadIdx.y;
    t[ty][tx] = W[(size_t)(k0 + ty) * 1024 + n0 + tx];
    __syncthreads();
    int n = n0 + ty;
    int destRow = (g == 0) ? n
                : (g == 1) ? 1024 + 2 * n
                : (g == 2) ? 1024 + 2 * n + 1
                :            3072 + n;
    g_wh[(size_t)destRow * 1024 + (k0 + tx)] = __float2half_rn(t[tx][ty]);
}

// ---------------- fp16 GEMM with register-local fused i*ig epilogue ----------------
// nTile 0..7: forget gate; 8..23: interleaved i/ig pair tiles; 24..31: output gate.
// B rows are uniformly contiguous: Bbase = g_wh + nTile*128*KTOT.
__global__ void __launch_bounds__(256, 2)
gemm_kernel(const float* __restrict__ bf, const float* __restrict__ bi,
            const float* __restrict__ big, const float* __restrict__ bog) {
    extern __shared__ __half sm[];
    const uint32_t sb = smem_u32(sm);

    const int tid  = threadIdx.x;
    const int wid  = tid >> 5, lane = tid & 31;
    const int lane4 = lane & 3, laneg = lane >> 2;
    const int warpM = wid & 3;          // 4 warps along M (32 rows each)
    const int warpN = wid >> 2;         // 2 warps along N (64 cols each)
    const int nTile = blockIdx.x;       // 0..31
    const int mTile = blockIdx.y;       // 0..255

    const __half* Abase = g_xh + (size_t)mTile * BM * KTOT;
    const __half* Bbase = g_wh + (size_t)nTile * 128 * KTOT;

    auto load_chunk = [&](int kc, int s) {
        const uint32_t sA = sb + s * (STAGE_H * 2);
        const uint32_t sB = sA + ASTAGE * 2;
        const __half* gA = Abase + kc * BK;
        const __half* gB = Bbase + kc * BK;
        #pragma unroll
        for (int i = 0; i < 4; i++) {                 // A: 1024 x 16B chunks
            int c = tid + i * 256;
            int row = c >> 3, seg = (c & 7) * 8;
            cp16(sA + (row * KP + seg) * 2, gA + (size_t)row * KTOT + seg);
        }
        #pragma unroll
        for (int i = 0; i < 4; i++) {                 // B: 1024 x 16B chunks
            int c = tid + i * 256;
            int row = c >> 3, seg = (c & 7) * 8;
            cp16(sB + (row * KP + seg) * 2, gB + (size_t)row * KTOT + seg);
        }
        cp_commit();
    };

    float acc[2][8][4];
    #pragma unroll
    for (int mf = 0; mf < 2; mf++)
        #pragma unroll
        for (int nf = 0; nf < 8; nf++)
            #pragma unroll
            for (int j = 0; j < 4; j++) acc[mf][nf][j] = 0.0f;

    uint32_t aOff[2], bOff[4];
    #pragma unroll
    for (int mf = 0; mf < 2; mf++)
        aOff[mf] = (uint32_t)(((warpM * 32 + mf * 16 + (lane & 15)) * KP + (lane >> 4) * 8) * 2);
    #pragma unroll
    for (int p = 0; p < 4; p++)
        bOff[p] = (uint32_t)(((warpN * 64 + p * 16 + (lane & 7) + (lane >> 4) * 8) * KP
                              + ((lane >> 3) & 1) * 8) * 2) + ASTAGE * 2;

    load_chunk(0, 0);
    load_chunk(1, 1);

    for (int kc = 0; kc < NKC; kc++) {
        const int s = kc % STAGES;
        if (kc + 1 < NKC) cp_wait<1>(); else cp_wait<0>();
        __syncthreads();
        if (kc + 2 < NKC) load_chunk(kc + 2, (kc + 2) % STAGES);

        const uint32_t st = sb + s * (STAGE_H * 2);
        #pragma unroll
        for (int kf = 0; kf < 4; kf++) {
            const uint32_t kb = kf * 32;
            uint32_t a[2][4];
            #pragma unroll
            for (int mf = 0; mf < 2; mf++)
                ldsm4(a[mf][0], a[mf][1], a[mf][2], a[mf][3], st + aOff[mf] + kb);
            uint32_t b[8][2];
            #pragma unroll
            for (int p = 0; p < 4; p++)
                ldsm4(b[2 * p][0], b[2 * p][1], b[2 * p + 1][0], b[2 * p + 1][1],
                      st + bOff[p] + kb);
            #pragma unroll
            for (int mf = 0; mf < 2; mf++)
                #pragma unroll
                for (int nf = 0; nf < 8; nf++)
                    mma_f16(acc[mf][nf][0], acc[mf][nf][1], acc[mf][nf][2], acc[mf][nf][3],
                            a[mf][0], a[mf][1], a[mf][2], a[mf][3],
                            b[nf][0], b[nf][1]);
        }
    }

    if (nTile >= 8 && nTile < 24) {
        // -------- register-local fused i*ig epilogue --------
        // acc[.][nf][0] = z_i(col j), acc[.][nf][1] = z_ig(col j), j = warpN*32 + nf*4 + lane4
        const int c0 = (nTile - 8) * 64;
        #pragma unroll
        for (int nf = 0; nf < 8; nf++) {
            const int j = warpN * 32 + nf * 4 + lane4;
            const float bz_i = bi[c0 + j], bz_g = big[c0 + j];
            #pragma unroll
            for (int mf = 0; mf < 2; mf++) {
                const int r0 = mTile * BM + warpM * 32 + mf * 16 + laneg;
                float i0 = tanhfast(acc[mf][nf][0] + bz_i) * sigf(acc[mf][nf][1] + bz_g);
                float i1 = tanhfast(acc[mf][nf][2] + bz_i) * sigf(acc[mf][nf][3] + bz_g);
                g_I[(size_t)r0 * DD + c0 + j]       = __float2half_rn(i0);
                g_I[(size_t)(r0 + 8) * DD + c0 + j] = __float2half_rn(i1);
            }
        }
    } else {
        // -------- plain sigmoid epilogue (f / og) --------
        const bool isF = (nTile < 8);
        const int nbase = isF ? nTile * 128 : (nTile - 24) * 128;
        const float* bias = isF ? bf : bog;
        __half* oA = isF ? g_f : g_og;
        #pragma unroll
        for (int nf = 0; nf < 8; nf++) {
            const int d = nbase + warpN * 64 + nf * 8 + 2 * lane4;
            const float bz0 = bias[d], bz1 = bias[d + 1];
            #pragma unroll
            for (int mf = 0; mf < 2; mf++) {
                const int r0 = mTile * BM + warpM * 32 + mf * 16 + laneg;
                float o0 = sigf(acc[mf][nf][0] + bz0);
                float o1 = sigf(acc[mf][nf][1] + bz1);
                float o2 = sigf(acc[mf][nf][2] + bz0);
                float o3 = sigf(acc[mf][nf][3] + bz1);
                *reinterpret_cast<__half2*>(oA + (size_t)r0 * DD + d) = __floats2half2_rn(o0, o1);
                *reinterpret_cast<__half2*>(oA + (size_t)(r0 + 8) * DD + d) = __floats2half2_rn(o2, o3);
            }
        }
    }
}

// ---------------- scan kernels (2 chains per thread via half2) ----------------
__global__ void scan_pass1() {
    int p = blockIdx.x * 256 + threadIdx.x;         // 0..511 half2 lane
    int c = blockIdx.y, b = blockIdx.z;
    size_t base = ((size_t)(b * LL + c * CL)) * (DD / 2) + p;
    const __half2* F2p = reinterpret_cast<const __half2*>(g_f);
    const __half2* I2p = reinterpret_cast<const __half2*>(g_I);
    float2 a = make_float2(1.0f, 1.0f);
    float2 s = make_float2(0.0f, 0.0f);
    for (int t = 0; t < CL; t++) {
        size_t idx = base + (size_t)t * (DD / 2);
        float2 F = __half22float2(F2p[idx]);
        float2 I = __half22float2(I2p[idx]);
        s.x = fmaf(F.x, s.x, I.x);
        s.y = fmaf(F.y, s.y, I.y);
        a.x *= F.x; a.y *= F.y;
    }
    int chain = b * DD + 2 * p;
    g_cA[c * NCHAIN + chain]     = a.x;
    g_cA[c * NCHAIN + chain + 1] = a.y;
    g_cB[c * NCHAIN + chain]     = s.x;
    g_cB[c * NCHAIN + chain + 1] = s.y;
}

__global__ void scan_pass2(const float* __restrict__ lh) {
    int chain = blockIdx.x * 256 + threadIdx.x;     // 0..4095
    float carry = lh[chain & (DD - 1)];
    for (int c = 0; c < NC; c++) {
        g_cr[c * NCHAIN + chain] = carry;
        carry = fmaf(g_cA[c * NCHAIN + chain], carry, g_cB[c * NCHAIN + chain]);
    }
}

__global__ void scan_pass3(float* __restrict__ y) {
    int p = blockIdx.x * 256 + threadIdx.x;         // 0..511 half2 lane
    int c = blockIdx.y, b = blockIdx.z;
    int chain = b * DD + 2 * p;
    float2 h;
    h.x = g_cr[c * NCHAIN + chain];
    h.y = g_cr[c * NCHAIN + chain + 1];
    size_t base = ((size_t)(b * LL + c * CL)) * (DD / 2) + p;
    const __half2* F2p  = reinterpret_cast<const __half2*>(g_f);
    const __half2* I2p  = reinterpret_cast<const __half2*>(g_I);
    const __half2* Og2p = reinterpret_cast<const __half2*>(g_og);
    for (int t = 0; t < CL; t++) {
        size_t idx = base + (size_t)t * (DD / 2);
        float2 F = __half22float2(F2p[idx]);
        float2 I = __half22float2(I2p[idx]);
        float2 Og = __half22float2(Og2p[idx]);
        h.x = fmaf(F.x, h.x, I.x);
        h.y = fmaf(F.y, h.y, I.y);
        float2 o;
        o.x = tanhfast(h.x) * Og.x;
        o.y = tanhfast(h.y) * Og.y;
        reinterpret_cast<float2*>(y)[idx] = o;
    }
}

// ---------------- launch ----------------
extern "C" void kernel_launch(void* const* d_in, const int* in_sizes, int n_in,
                              void* d_out, int out_size) {
    const float* x   = (const float*)d_in[0];
    const float* Wf  = (const float*)d_in[1];
    const float* bf  = (const float*)d_in[2];
    const float* Wi  = (const float*)d_in[3];
    const float* bi  = (const float*)d_in[4];
    const float* Wig = (const float*)d_in[5];
    const float* big = (const float*)d_in[6];
    const float* Wog = (const float*)d_in[7];
    const float* bog = (const float*)d_in[8];
    const float* lh  = (const float*)d_in[9];
    float* y = (float*)d_out;

    cudaFuncSetAttribute(gemm_kernel, cudaFuncAttributeMaxDynamicSharedMemorySize, SMEM_BYTES);

    prep_x_kernel<<<16384, 256>>>(x);
    prep_w_kernel<<<dim3(32, 32, 4), dim3(32, 32)>>>(Wf, Wi, Wig, Wog);
    gemm_kernel<<<dim3(32, 256), 256, SMEM_BYTES>>>(bf, bi, big, bog);
    scan_pass1<<<dim3(2, NC, 4), 256>>>();
    scan_pass2<<<16, 256>>>(lh);
    scan_pass3<<<dim3(2, NC, 4), 256>>>(y);
}

// round 17
// speedup vs baseline: 1.0783x; 1.0276x over previous
#include <cuda_runtime.h>
#include <cuda_fp16.h>
#include <cstdint>
#include <math.h>

#define DI __device__ __forceinline__

// ---------------- problem sizes ----------------
constexpr int BB   = 4;
constexpr int LL   = 8192;
constexpr int DD   = 1024;
constexpr int MTOT = BB * LL;     // 32768
constexpr int KTOT = 1024;

// GEMM tiling: 128x128 CTA tile, 8 warps (4Mx2N), 32x64 warp tiles, BK=64, 2 CTAs/SM
constexpr int BM = 128, BN = 128, BK = 64;
constexpr int NKC = KTOT / BK;            // 16
constexpr int KP  = 72;                   // smem pitch in halfs (144B rows, conflict-free)
constexpr int ASTAGE = BM * KP;           // 9216 halfs
constexpr int BSTAGE = BN * KP;           // 9216 halfs
constexpr int STAGE_H = ASTAGE + BSTAGE;  // 18432 halfs = 36864 B
constexpr int STAGES = 3;
constexpr int SMEM_BYTES = STAGES * STAGE_H * 2;   // 110592 B -> 2 CTAs/SM
constexpr int SP = 72;                    // pair-tile staging pitch (halfs, 144B rows)
constexpr int FP = 136;                   // f/og staging pitch (halfs, 272B rows)

// scan chunking
constexpr int NC = 128;
constexpr int CL = LL / NC;               // 64
constexpr int NCHAIN = BB * DD;           // 4096

// ---------------- device scratch ----------------
// g_wh row layout: [0,1024) = W_f; [1024,3072) = interleaved W_i/W_ig; [3072,4096) = W_og
__device__ __half g_xh[(size_t)MTOT * KTOT];    // fp16 x
__device__ __half g_wh[(size_t)4 * DD * KTOT];  // fp16 weights [n][k]
__device__ __half g_f [(size_t)MTOT * DD];      // sigmoid forget gate (fp16)
__device__ __half g_I [(size_t)MTOT * DD];      // tanh(zi)*sig(zig) fused input (fp16)
__device__ __half g_og[(size_t)MTOT * DD];      // sigmoid output gate (fp16)
__device__ float g_cA[NC * NCHAIN];
__device__ float g_cB[NC * NCHAIN];
__device__ float g_cr[NC * NCHAIN];

// ---------------- helpers ----------------
DI uint32_t smem_u32(const void* p) {
    uint32_t a;
    asm("{ .reg .u64 t; cvta.to.shared.u64 t, %1; cvt.u32.u64 %0, t; }" : "=r"(a) : "l"(p));
    return a;
}
DI void cp16(uint32_t dst, const void* src) {
    asm volatile("cp.async.cg.shared.global [%0], [%1], 16;" :: "r"(dst), "l"(src));
}
DI void cp_commit() { asm volatile("cp.async.commit_group;" ::: "memory"); }
template <int N> DI void cp_wait() {
    asm volatile("cp.async.wait_group %0;" :: "n"(N) : "memory");
}
DI void ldsm4(uint32_t& r0, uint32_t& r1, uint32_t& r2, uint32_t& r3, uint32_t addr) {
    asm volatile("ldmatrix.sync.aligned.m8n8.x4.shared.b16 {%0,%1,%2,%3}, [%4];"
                 : "=r"(r0), "=r"(r1), "=r"(r2), "=r"(r3) : "r"(addr));
}
DI void mma_f16(float& c0, float& c1, float& c2, float& c3,
                uint32_t a0, uint32_t a1, uint32_t a2, uint32_t a3,
                uint32_t b0, uint32_t b1) {
    asm volatile(
        "mma.sync.aligned.m16n8k16.row.col.f32.f16.f16.f32 "
        "{%0,%1,%2,%3}, {%4,%5,%6,%7}, {%8,%9}, {%0,%1,%2,%3};"
        : "+f"(c0), "+f"(c1), "+f"(c2), "+f"(c3)
        : "r"(a0), "r"(a1), "r"(a2), "r"(a3), "r"(b0), "r"(b1));
}
DI float sigf(float z) { return 1.0f / (1.0f + __expf(-z)); }
DI float tanhfast(float z) { return 1.0f - 2.0f / (1.0f + __expf(2.0f * z)); }

// ---------------- prep: fp32 -> fp16 ----------------
__global__ void prep_x_kernel(const float* __restrict__ x) {
    size_t i = (size_t)blockIdx.x * blockDim.x + threadIdx.x;
    float4 v0 = reinterpret_cast<const float4*>(x)[2 * i];
    float4 v1 = reinterpret_cast<const float4*>(x)[2 * i + 1];
    __half2 h[4];
    h[0] = __floats2half2_rn(v0.x, v0.y);
    h[1] = __floats2half2_rn(v0.z, v0.w);
    h[2] = __floats2half2_rn(v1.x, v1.y);
    h[3] = __floats2half2_rn(v1.z, v1.w);
    reinterpret_cast<uint4*>(g_xh)[i] = *reinterpret_cast<uint4*>(h);
}

__global__ void prep_w_kernel(const float* __restrict__ Wf, const float* __restrict__ Wi,
                              const float* __restrict__ Wig, const float* __restrict__ Wog) {
    __shared__ float t[32][33];
    int g = blockIdx.z;
    const float* W = (g == 0) ? Wf : (g == 1) ? Wi : (g == 2) ? Wig : Wog;
    int n0 = blockIdx.x * 32, k0 = blockIdx.y * 32;
    int tx = threadIdx.x, ty = threadIdx.y;
    t[ty][tx] = W[(size_t)(k0 + ty) * 1024 + n0 + tx];
    __syncthreads();
    int n = n0 + ty;
    int destRow = (g == 0) ? n
                : (g == 1) ? 1024 + 2 * n
                : (g == 2) ? 1024 + 2 * n + 1
                :            3072 + n;
    g_wh[(size_t)destRow * 1024 + (k0 + tx)] = __float2half_rn(t[tx][ty]);
}

// ---------------- fp16 GEMM, fused i*ig epilogue, smem-staged stores ----------------
__global__ void __launch_bounds__(256, 2)
gemm_kernel(const float* __restrict__ bf, const float* __restrict__ bi,
            const float* __restrict__ big, const float* __restrict__ bog) {
    extern __shared__ __half sm[];
    const uint32_t sb = smem_u32(sm);

    const int tid  = threadIdx.x;
    const int wid  = tid >> 5, lane = tid & 31;
    const int lane4 = lane & 3, laneg = lane >> 2;
    const int warpM = wid & 3;          // 4 warps along M (32 rows each)
    const int warpN = wid >> 2;         // 2 warps along N (64 cols each)
    const int nTile = blockIdx.x;       // 0..31
    const int mTile = blockIdx.y;       // 0..255

    const __half* Abase = g_xh + (size_t)mTile * BM * KTOT;
    const __half* Bbase = g_wh + (size_t)nTile * 128 * KTOT;

    auto load_chunk = [&](int kc, int s) {
        const uint32_t sA = sb + s * (STAGE_H * 2);
        const uint32_t sB = sA + ASTAGE * 2;
        const __half* gA = Abase + kc * BK;
        const __half* gB = Bbase + kc * BK;
        #pragma unroll
        for (int i = 0; i < 4; i++) {                 // A: 1024 x 16B chunks
            int c = tid + i * 256;
            int row = c >> 3, seg = (c & 7) * 8;
            cp16(sA + (row * KP + seg) * 2, gA + (size_t)row * KTOT + seg);
        }
        #pragma unroll
        for (int i = 0; i < 4; i++) {                 // B: 1024 x 16B chunks
            int c = tid + i * 256;
            int row = c >> 3, seg = (c & 7) * 8;
            cp16(sB + (row * KP + seg) * 2, gB + (size_t)row * KTOT + seg);
        }
        cp_commit();
    };

    float acc[2][8][4];
    #pragma unroll
    for (int mf = 0; mf < 2; mf++)
        #pragma unroll
        for (int nf = 0; nf < 8; nf++)
            #pragma unroll
            for (int j = 0; j < 4; j++) acc[mf][nf][j] = 0.0f;

    uint32_t aOff[2], bOff[4];
    #pragma unroll
    for (int mf = 0; mf < 2; mf++)
        aOff[mf] = (uint32_t)(((warpM * 32 + mf * 16 + (lane & 15)) * KP + (lane >> 4) * 8) * 2);
    #pragma unroll
    for (int p = 0; p < 4; p++)
        bOff[p] = (uint32_t)(((warpN * 64 + p * 16 + (lane & 7) + (lane >> 4) * 8) * KP
                              + ((lane >> 3) & 1) * 8) * 2) + ASTAGE * 2;

    load_chunk(0, 0);
    load_chunk(1, 1);

    for (int kc = 0; kc < NKC; kc++) {
        const int s = kc % STAGES;
        if (kc + 1 < NKC) cp_wait<1>(); else cp_wait<0>();
        __syncthreads();

        const uint32_t st = sb + s * (STAGE_H * 2);

        // ---- kf = 0 fragments first (their latency is hidden by cp.async issue) ----
        uint32_t a0[2][4], b0[8][2];
        #pragma unroll
        for (int mf = 0; mf < 2; mf++)
            ldsm4(a0[mf][0], a0[mf][1], a0[mf][2], a0[mf][3], st + aOff[mf]);
        #pragma unroll
        for (int p = 0; p < 4; p++)
            ldsm4(b0[2 * p][0], b0[2 * p][1], b0[2 * p + 1][0], b0[2 * p + 1][1],
                  st + bOff[p]);

        if (kc + 2 < NKC) load_chunk(kc + 2, (kc + 2) % STAGES);

        #pragma unroll
        for (int mf = 0; mf < 2; mf++)
            #pragma unroll
            for (int nf = 0; nf < 8; nf++)
                mma_f16(acc[mf][nf][0], acc[mf][nf][1], acc[mf][nf][2], acc[mf][nf][3],
                        a0[mf][0], a0[mf][1], a0[mf][2], a0[mf][3],
                        b0[nf][0], b0[nf][1]);

        #pragma unroll
        for (int kf = 1; kf < 4; kf++) {
            const uint32_t kb = kf * 32;
            uint32_t a[2][4];
            #pragma unroll
            for (int mf = 0; mf < 2; mf++)
                ldsm4(a[mf][0], a[mf][1], a[mf][2], a[mf][3], st + aOff[mf] + kb);
            uint32_t b[8][2];
            #pragma unroll
            for (int p = 0; p < 4; p++)
                ldsm4(b[2 * p][0], b[2 * p][1], b[2 * p + 1][0], b[2 * p + 1][1],
                      st + bOff[p] + kb);
            #pragma unroll
            for (int mf = 0; mf < 2; mf++)
                #pragma unroll
                for (int nf = 0; nf < 8; nf++)
                    mma_f16(acc[mf][nf][0], acc[mf][nf][1], acc[mf][nf][2], acc[mf][nf][3],
                            a[mf][0], a[mf][1], a[mf][2], a[mf][3],
                            b[nf][0], b[nf][1]);
        }
    }

    __syncthreads();   // all warps done reading stage smem; reuse it for staging

    if (nTile >= 8 && nTile < 24) {
        // -------- register-local fused i*ig epilogue, staged through smem --------
        const int c0 = (nTile - 8) * 64;
        #pragma unroll
        for (int nf = 0; nf < 8; nf++) {
            const int j = warpN * 32 + nf * 4 + lane4;
            const float bz_i = bi[c0 + j], bz_g = big[c0 + j];
            #pragma unroll
            for (int mf = 0; mf < 2; mf++) {
                const int rl = warpM * 32 + mf * 16 + laneg;
                float i0 = tanhfast(acc[mf][nf][0] + bz_i) * sigf(acc[mf][nf][1] + bz_g);
                float i1 = tanhfast(acc[mf][nf][2] + bz_i) * sigf(acc[mf][nf][3] + bz_g);
                sm[rl * SP + j]       = __float2half_rn(i0);
                sm[(rl + 8) * SP + j] = __float2half_rn(i1);
            }
        }
        __syncthreads();
        #pragma unroll
        for (int it = 0; it < 4; it++) {
            int t = tid + it * 256;               // 0..1023
            int row = t >> 3, ch = t & 7;
            uint4 v = *reinterpret_cast<const uint4*>(sm + row * SP + ch * 8);
            *reinterpret_cast<uint4*>(g_I + (size_t)(mTile * BM + row) * DD + c0 + ch * 8) = v;
        }
    } else {
        // -------- plain sigmoid epilogue (f / og), staged through smem --------
        const bool isF = (nTile < 8);
        const int nbase = isF ? nTile * 128 : (nTile - 24) * 128;
        const float* bias = isF ? bf : bog;
        __half* oA = isF ? g_f : g_og;
        #pragma unroll
        for (int nf = 0; nf < 8; nf++) {
            const int d = warpN * 64 + nf * 8 + 2 * lane4;
            const float bz0 = bias[nbase + d], bz1 = bias[nbase + d + 1];
            #pragma unroll
            for (int mf = 0; mf < 2; mf++) {
                const int rl = warpM * 32 + mf * 16 + laneg;
                float o0 = sigf(acc[mf][nf][0] + bz0);
                float o1 = sigf(acc[mf][nf][1] + bz1);
                float o2 = sigf(acc[mf][nf][2] + bz0);
                float o3 = sigf(acc[mf][nf][3] + bz1);
                *reinterpret_cast<__half2*>(sm + rl * FP + d)       = __floats2half2_rn(o0, o1);
                *reinterpret_cast<__half2*>(sm + (rl + 8) * FP + d) = __floats2half2_rn(o2, o3);
            }
        }
        __syncthreads();
        #pragma unroll
        for (int it = 0; it < 8; it++) {
            int t = tid + it * 256;               // 0..2047
            int row = t >> 4, ch = t & 15;
            uint4 v = *reinterpret_cast<const uint4*>(sm + row * FP + ch * 8);
            *reinterpret_cast<uint4*>(oA + (size_t)(mTile * BM + row) * DD + nbase + ch * 8) = v;
        }
    }
}

// ---------------- scan kernels (2 chains per thread via half2) ----------------
__global__ void scan_pass1() {
    int p = blockIdx.x * 256 + threadIdx.x;         // 0..511 half2 lane
    int c = blockIdx.y, b = blockIdx.z;
    size_t base = ((size_t)(b * LL + c * CL)) * (DD / 2) + p;
    const __half2* F2p = reinterpret_cast<const __half2*>(g_f);
    const __half2* I2p = reinterpret_cast<const __half2*>(g_I);
    float2 a = make_float2(1.0f, 1.0f);
    float2 s = make_float2(0.0f, 0.0f);
    for (int t = 0; t < CL; t++) {
        size_t idx = base + (size_t)t * (DD / 2);
        float2 F = __half22float2(F2p[idx]);
        float2 I = __half22float2(I2p[idx]);
        s.x = fmaf(F.x, s.x, I.x);
        s.y = fmaf(F.y, s.y, I.y);
        a.x *= F.x; a.y *= F.y;
    }
    int chain = b * DD + 2 * p;
    g_cA[c * NCHAIN + chain]     = a.x;
    g_cA[c * NCHAIN + chain + 1] = a.y;
    g_cB[c * NCHAIN + chain]     = s.x;
    g_cB[c * NCHAIN + chain + 1] = s.y;
}

__global__ void scan_pass2(const float* __restrict__ lh) {
    int chain = blockIdx.x * 256 + threadIdx.x;     // 0..4095
    float carry = lh[chain & (DD - 1)];
    for (int c = 0; c < NC; c++) {
        g_cr[c * NCHAIN + chain] = carry;
        carry = fmaf(g_cA[c * NCHAIN + chain], carry, g_cB[c * NCHAIN + chain]);
    }
}

__global__ void scan_pass3(float* __restrict__ y) {
    int p = blockIdx.x * 256 + threadIdx.x;         // 0..511 half2 lane
    int c = blockIdx.y, b = blockIdx.z;
    int chain = b * DD + 2 * p;
    float2 h;
    h.x = g_cr[c * NCHAIN + chain];
    h.y = g_cr[c * NCHAIN + chain + 1];
    size_t base = ((size_t)(b * LL + c * CL)) * (DD / 2) + p;
    const __half2* F2p  = reinterpret_cast<const __half2*>(g_f);
    const __half2* I2p  = reinterpret_cast<const __half2*>(g_I);
    const __half2* Og2p = reinterpret_cast<const __half2*>(g_og);
    for (int t = 0; t < CL; t++) {
        size_t idx = base + (size_t)t * (DD / 2);
        float2 F = __half22float2(F2p[idx]);
        float2 I = __half22float2(I2p[idx]);
        float2 Og = __half22float2(Og2p[idx]);
        h.x = fmaf(F.x, h.x, I.x);
        h.y = fmaf(F.y, h.y, I.y);
        float2 o;
        o.x = tanhfast(h.x) * Og.x;
        o.y = tanhfast(h.y) * Og.y;
        reinterpret_cast<float2*>(y)[idx] = o;
    }
}

// ---------------- launch ----------------
extern "C" void kernel_launch(void* const* d_in, const int* in_sizes, int n_in,
                              void* d_out, int out_size) {
    const float* x   = (const float*)d_in[0];
    const float* Wf  = (const float*)d_in[1];
    const float* bf  = (const float*)d_in[2];
    const float* Wi  = (const float*)d_in[3];
    const float* bi  = (const float*)d_in[4];
    const float* Wig = (const float*)d_in[5];
    const float* big = (const float*)d_in[6];
    const float* Wog = (const float*)d_in[7];
    const float* bog = (const float*)d_in[8];
    const float* lh  = (const float*)d_in[9];
    float* y = (float*)d_out;

    cudaFuncSetAttribute(gemm_kernel, cudaFuncAttributeMaxDynamicSharedMemorySize, SMEM_BYTES);

    prep_x_kernel<<<16384, 256>>>(x);
    prep_w_kernel<<<dim3(32, 32, 4), dim3(32, 32)>>>(Wf, Wi, Wig, Wog);
    gemm_kernel<<<dim3(32, 256), 256, SMEM_BYTES>>>(bf, bi, big, bog);
    scan_pass1<<<dim3(2, NC, 4), 256>>>();
    scan_pass2<<<16, 256>>>(lh);
    scan_pass3<<<dim3(2, NC, 4), 256>>>(y);
}